// round 1
// baseline (speedup 1.0000x reference)
#include <cuda_runtime.h>
#include <cstddef>

#define Bn 16
#define Nn 2048
#define Cn 128
#define NP 512
#define CIN 131
#define CMID 32
#define COUT 128
#define CPW2 160          // padded W2 row (32x160 in smem, zeros beyond 131)
#define PROW 132          // pooled row stride
#define NROWS (3*Bn*NP)   // 24576 pooled rows

__device__ float g_featT[Bn*Nn*Cn];      // 16 MB scratch: features transposed (B,N,C)
__device__ float g_pooled[NROWS*PROW];   // 13 MB scratch: pooled (row = s*8192 + b*512 + p)

// ---------------------------------------------------------------------------
// K0: transpose features (B,C,N) -> featT (B,N,C), tiled for coalescing
// ---------------------------------------------------------------------------
__global__ void k_transpose(const float* __restrict__ f) {
    __shared__ float tile[32][33];
    int b  = blockIdx.z;
    int c0 = blockIdx.x * 32, n0 = blockIdx.y * 32;
    int tx = threadIdx.x, ty = threadIdx.y;
    const float* src = f + (size_t)b * Cn * Nn;
    float* dst = g_featT + (size_t)b * Nn * Cn;
#pragma unroll
    for (int j = 0; j < 32; j += 8)
        tile[ty + j][tx] = src[(size_t)(c0 + ty + j) * Nn + n0 + tx];
    __syncthreads();
#pragma unroll
    for (int j = 0; j < 32; j += 8)
        dst[(size_t)(n0 + ty + j) * Cn + c0 + tx] = tile[tx][ty + j];
}

// ---------------------------------------------------------------------------
// K1: farthest point sampling. One block per batch. Bit-exact distances
// (no FMA contraction), argmax ties -> lowest index (jnp.argmax semantics).
// Writes new_xyz directly into d_out's first region.
// ---------------------------------------------------------------------------
__global__ __launch_bounds__(1024) void k_fps(const float* __restrict__ xyz,
                                              float* __restrict__ out_xyz) {
    __shared__ float xs[Nn], ys[Nn], zs[Nn];
    __shared__ float rv[32];
    __shared__ int   ri[32];
    __shared__ int   nxt_sh;
    int b = blockIdx.x, tid = threadIdx.x;
    int lane = tid & 31, wid = tid >> 5;
    const float* src = xyz + (size_t)b * Nn * 3;
    for (int t = tid; t < Nn; t += 1024) {
        xs[t] = src[t*3 + 0]; ys[t] = src[t*3 + 1]; zs[t] = src[t*3 + 2];
    }
    __syncthreads();
    int i0 = tid, i1 = tid + 1024;
    float x0 = xs[i0], y0 = ys[i0], z0 = zs[i0];
    float x1 = xs[i1], y1 = ys[i1], z1 = zs[i1];
    float d0 = 1e10f, d1 = 1e10f;
    int last = 0;
    if (tid == 0) {
        out_xyz[(size_t)b*NP*3 + 0] = xs[0];
        out_xyz[(size_t)b*NP*3 + 1] = ys[0];
        out_xyz[(size_t)b*NP*3 + 2] = zs[0];
    }
    for (int it = 1; it < NP; ++it) {
        float px = xs[last], py = ys[last], pz = zs[last];
        float ax = x0 - px, ay = y0 - py, az = z0 - pz;
        float dd = __fadd_rn(__fadd_rn(__fmul_rn(ax,ax), __fmul_rn(ay,ay)), __fmul_rn(az,az));
        d0 = fminf(d0, dd);
        ax = x1 - px; ay = y1 - py; az = z1 - pz;
        dd = __fadd_rn(__fadd_rn(__fmul_rn(ax,ax), __fmul_rn(ay,ay)), __fmul_rn(az,az));
        d1 = fminf(d1, dd);
        float v; int ix;
        if (d1 > d0) { v = d1; ix = i1; } else { v = d0; ix = i0; }
#pragma unroll
        for (int off = 16; off; off >>= 1) {
            float ov = __shfl_xor_sync(0xffffffffu, v, off);
            int   oi = __shfl_xor_sync(0xffffffffu, ix, off);
            if (ov > v || (ov == v && oi < ix)) { v = ov; ix = oi; }
        }
        if (lane == 0) { rv[wid] = v; ri[wid] = ix; }
        __syncthreads();
        if (wid == 0) {
            v = rv[lane]; ix = ri[lane];
#pragma unroll
            for (int off = 16; off; off >>= 1) {
                float ov = __shfl_xor_sync(0xffffffffu, v, off);
                int   oi = __shfl_xor_sync(0xffffffffu, ix, off);
                if (ov > v || (ov == v && oi < ix)) { v = ov; ix = oi; }
            }
            if (lane == 0) {
                nxt_sh = ix;
                out_xyz[(size_t)(b*NP + it)*3 + 0] = xs[ix];
                out_xyz[(size_t)(b*NP + it)*3 + 1] = ys[ix];
                out_xyz[(size_t)(b*NP + it)*3 + 2] = zs[ix];
            }
        }
        __syncthreads();
        last = nxt_sh;
    }
}

// ---------------------------------------------------------------------------
// K2 (fused): ball query (3 scales, warps 0-2) + pointwise MLP + relu(h*x)
// max-pool per (b, center). 4 samples per warp iteration to amortize W2
// shared reads. Writes pooled[3][131] per center to g_pooled.
// ---------------------------------------------------------------------------
__global__ __launch_bounds__(160) void k_msg(const float* __restrict__ xyz,
                                             const float* __restrict__ W1,
                                             const float* __restrict__ b1,
                                             const float* __restrict__ W2,
                                             const float* __restrict__ b2,
                                             const float* __restrict__ new_xyz) {
    __shared__ float W1s[10*32];
    __shared__ float b1s[32];
    __shared__ float W2s[32*CPW2];
    __shared__ float b2s[CPW2];
    __shared__ int   idx_sh[96];
    __shared__ float h1buf[5*32*4];
    __shared__ int   pooled_sh[3*132];
    int tid = threadIdx.x, lane = tid & 31, w = tid >> 5;
    int blk = blockIdx.x, b = blk >> 9;
    const float* bp  = xyz + (size_t)b * Nn * 3;

    for (int i = tid; i < 320; i += 160) W1s[i] = W1[i];
    if (tid < 32) b1s[tid] = b1[tid];
    for (int i = tid; i < 32*CPW2; i += 160) {
        int m = i / CPW2, c = i - m * CPW2;
        W2s[i] = (c < CIN) ? W2[m*CIN + c] : 0.f;
    }
    for (int i = tid; i < CPW2; i += 160) b2s[i] = (i < CIN) ? b2[i] : 0.f;
    for (int i = tid; i < 3*132; i += 160) pooled_sh[i] = 0;

    float cx = new_xyz[(size_t)blk*3 + 0];
    float cy = new_xyz[(size_t)blk*3 + 1];
    float cz = new_xyz[(size_t)blk*3 + 2];

    // ---- ball query: first `ns` indices (ascending) with d2 < r^2, pad w/ first
    if (w < 3) {
        const float thr = (w == 0) ? (float)(0.1*0.1) : (w == 1) ? (float)(0.2*0.2) : (float)(0.4*0.4);
        const int   ns  = (w == 0) ? 16 : (w == 1) ? 32 : 48;
        const int   off = (w == 0) ? 0  : (w == 1) ? 16 : 48;
        int cnt = 0;
        for (int ch = 0; ch < 64 && cnt < ns; ++ch) {
            int i = ch*32 + lane;
            float qx = bp[i*3 + 0], qy = bp[i*3 + 1], qz = bp[i*3 + 2];
            float ax = cx - qx, ay = cy - qy, az = cz - qz;
            float d2 = __fadd_rn(__fadd_rn(__fmul_rn(ax,ax), __fmul_rn(ay,ay)), __fmul_rn(az,az));
            bool pr = d2 < thr;
            unsigned mk = __ballot_sync(0xffffffffu, pr);
            if (pr) {
                int pos = cnt + __popc(mk & ((1u << lane) - 1u));
                if (pos < ns) idx_sh[off + pos] = i;
            }
            cnt += __popc(mk);
        }
        __syncwarp();
        if (cnt < ns) {
            int f0 = idx_sh[off];   // at least 1 always in-radius (the center itself)
            for (int q = cnt + lane; q < ns; q += 32) idx_sh[off + q] = f0;
        }
    }
    __syncthreads();

    // ---- MLP + pooling: 24 groups of 4 samples, round-robin over 5 warps
    const float* ftb = g_featT + (size_t)b * Nn * Cn;
    for (int g = w; g < 24; g += 5) {
        int s, sb, j0;
        if (g < 4)       { s = 0; sb = 0;  j0 = g * 4; }
        else if (g < 12) { s = 1; sb = 16; j0 = (g - 4) * 4; }
        else             { s = 2; sb = 48; j0 = (g - 12) * 4; }
        int sidx[4]; float relx[4], rely[4], relz[4], h1v[4];
#pragma unroll
        for (int q = 0; q < 4; ++q) {
            int ii = idx_sh[sb + j0 + q];
            sidx[q] = ii;
            float gx = bp[ii*3 + 0], gy = bp[ii*3 + 1], gz = bp[ii*3 + 2];
            float rx = gx - cx, ry = gy - cy, rz = gz - cz;
            relx[q] = rx; rely[q] = ry; relz[q] = rz;
            float dn = sqrtf(rx*rx + ry*ry + rz*rz);
            // h10 = [dn, cx,cy,cz, gx,gy,gz, rx,ry,rz]; lane m computes h1[m]
            float a = b1s[lane];
            a = fmaf(dn, W1s[0*32 + lane], a);
            a = fmaf(cx, W1s[1*32 + lane], a);
            a = fmaf(cy, W1s[2*32 + lane], a);
            a = fmaf(cz, W1s[3*32 + lane], a);
            a = fmaf(gx, W1s[4*32 + lane], a);
            a = fmaf(gy, W1s[5*32 + lane], a);
            a = fmaf(gz, W1s[6*32 + lane], a);
            a = fmaf(rx, W1s[7*32 + lane], a);
            a = fmaf(ry, W1s[8*32 + lane], a);
            a = fmaf(rz, W1s[9*32 + lane], a);
            h1v[q] = fmaxf(a, 0.f);
        }
        __syncwarp();
        *(float4*)&h1buf[(w*32 + lane)*4] = make_float4(h1v[0], h1v[1], h1v[2], h1v[3]);
        __syncwarp();

        float acc[5][4];
#pragma unroll
        for (int i = 0; i < 5; ++i) {
            float bb = b2s[i*32 + lane];
            acc[i][0] = bb; acc[i][1] = bb; acc[i][2] = bb; acc[i][3] = bb;
        }
#pragma unroll 4
        for (int m = 0; m < 32; ++m) {
            float4 H = *(const float4*)&h1buf[(w*32 + m)*4];
#pragma unroll
            for (int i = 0; i < 5; ++i) {
                float ww = W2s[m*CPW2 + i*32 + lane];
                acc[i][0] = fmaf(ww, H.x, acc[i][0]);
                acc[i][1] = fmaf(ww, H.y, acc[i][1]);
                acc[i][2] = fmaf(ww, H.z, acc[i][2]);
                acc[i][3] = fmaf(ww, H.w, acc[i][3]);
            }
        }
#pragma unroll
        for (int i = 0; i < 5; ++i) {
            int c = i*32 + lane;
            if (c < CIN) {
                float vmax = 0.f;
#pragma unroll
                for (int q = 0; q < 4; ++q) {
                    float xv;
                    if (c >= 3) xv = ftb[(size_t)sidx[q]*Cn + (c - 3)];
                    else        xv = (c == 0) ? relx[q] : (c == 1) ? rely[q] : relz[q];
                    float v = acc[i][q] * xv;
                    vmax = fmaxf(vmax, fmaxf(v, 0.f));
                }
                atomicMax(&pooled_sh[s*132 + c], __float_as_int(vmax)); // vmax >= 0
            }
        }
    }
    __syncthreads();
    for (int i = tid; i < 3*CIN; i += 160) {
        int s = i / CIN, c = i - s*CIN;
        g_pooled[(size_t)(s*8192 + blk)*PROW + c] = __int_as_float(pooled_sh[s*132 + c]);
    }
}

// ---------------------------------------------------------------------------
// K3: out = relu(pooled @ Wcr + bcr), M=24576 K=131 N=128, tiled GEMM.
// Writes transposed layout new_features[b][s*128+o][p] into d_out.
// ---------------------------------------------------------------------------
__global__ __launch_bounds__(256) void k_proj(const float* __restrict__ Wcr,
                                              const float* __restrict__ bcr,
                                              float* __restrict__ outF) {
    __shared__ float Ps[131*36];   // transposed pooled tile: [k][r], stride 36
    __shared__ float Wp[32*128];   // Wcr k-panel
    __shared__ float bs[128];
    int tid = threadIdx.x;
    int row0 = blockIdx.x * 32;
    for (int idx = tid; idx < 32*131; idx += 256) {
        int r = idx / 131, k = idx - r*131;
        Ps[k*36 + r] = g_pooled[(size_t)(row0 + r)*PROW + k];
    }
    if (tid < 128) bs[tid] = bcr[tid];
    float acc[4][4];
#pragma unroll
    for (int r = 0; r < 4; ++r)
#pragma unroll
        for (int o = 0; o < 4; ++o) acc[r][o] = 0.f;
    int cg = tid & 31, rg = tid >> 5;
    for (int kp = 0; kp < 5; ++kp) {
        int kb = kp*32;
        int klen = (kp == 4) ? 3 : 32;
        __syncthreads();
        for (int idx = tid; idx < klen*128; idx += 256) Wp[idx] = Wcr[kb*128 + idx];
        __syncthreads();
        for (int kk = 0; kk < klen; ++kk) {
            float4 wv = *(const float4*)&Wp[kk*128 + cg*4];
            float4 av = *(const float4*)&Ps[(kb + kk)*36 + rg*4];
            acc[0][0] = fmaf(av.x, wv.x, acc[0][0]);
            acc[0][1] = fmaf(av.x, wv.y, acc[0][1]);
            acc[0][2] = fmaf(av.x, wv.z, acc[0][2]);
            acc[0][3] = fmaf(av.x, wv.w, acc[0][3]);
            acc[1][0] = fmaf(av.y, wv.x, acc[1][0]);
            acc[1][1] = fmaf(av.y, wv.y, acc[1][1]);
            acc[1][2] = fmaf(av.y, wv.z, acc[1][2]);
            acc[1][3] = fmaf(av.y, wv.w, acc[1][3]);
            acc[2][0] = fmaf(av.z, wv.x, acc[2][0]);
            acc[2][1] = fmaf(av.z, wv.y, acc[2][1]);
            acc[2][2] = fmaf(av.z, wv.z, acc[2][2]);
            acc[2][3] = fmaf(av.z, wv.w, acc[2][3]);
            acc[3][0] = fmaf(av.w, wv.x, acc[3][0]);
            acc[3][1] = fmaf(av.w, wv.y, acc[3][1]);
            acc[3][2] = fmaf(av.w, wv.z, acc[3][2]);
            acc[3][3] = fmaf(av.w, wv.w, acc[3][3]);
        }
    }
#pragma unroll
    for (int rr = 0; rr < 4; ++rr) {
        int row = row0 + rg*4 + rr;
        int s  = row >> 13;
        int bb = (row >> 9) & 15;
        int pp = row & 511;
        size_t obase = (size_t)bb*(384*512) + (size_t)(s*128)*512 + pp;
#pragma unroll
        for (int oo = 0; oo < 4; ++oo) {
            float v = acc[rr][oo] + bs[cg*4 + oo];
            outF[obase + (size_t)(cg*4 + oo)*512] = fmaxf(v, 0.f);
        }
    }
}

// ---------------------------------------------------------------------------
extern "C" void kernel_launch(void* const* d_in, const int* in_sizes, int n_in,
                              void* d_out, int out_size) {
    const float* xyz  = (const float*)d_in[0];
    const float* feat = (const float*)d_in[1];
    const float* W1   = (const float*)d_in[2];
    const float* b1   = (const float*)d_in[3];
    const float* W2   = (const float*)d_in[4];
    const float* b2   = (const float*)d_in[5];
    const float* Wcr  = (const float*)d_in[6];
    const float* bcr  = (const float*)d_in[7];
    float* out      = (float*)d_out;
    float* out_xyz  = out;                 // (B,512,3) region
    float* outF     = out + Bn*NP*3;       // (B,384,512) region

    k_transpose<<<dim3(4, 64, 16), dim3(32, 8)>>>(feat);
    k_fps<<<16, 1024>>>(xyz, out_xyz);
    k_msg<<<8192, 160>>>(xyz, W1, b1, W2, b2, out_xyz);
    k_proj<<<768, 256>>>(Wcr, bcr, outF);
}